// round 16
// baseline (speedup 1.0000x reference)
#include <cuda_runtime.h>
#include <cuda_bf16.h>
#include <cstdint>

// Inputs (metadata order):
//   d_in[0] : energy_readout            float32 [262144]
//   d_in[1] : atomic_numbers            int32   [8388608]
//   d_in[2] : atomic_subsystem_indices  int32   [8388608]  (sorted ascending)
//   d_in[3] : self_energies_tensor      float32 [100]
// Output: float32 [262144] = energy_readout + segment_sum(se[Z], seg_idx)

#define TPB 256
#define TILE_ATOMS 2048                 // atoms per tile
#define TILE_BYTES (TILE_ATOMS * 4)     // 8192 B per array
#define STAGE_BYTES (2 * TILE_BYTES)    // z + seg = 16384 B
#define TILES_PER_CTA 4                 // all 4 stages issued up-front
#define SMEM_DYN (TILES_PER_CTA * STAGE_BYTES)  // 64 KB

__global__ void init_out_kernel(const float* __restrict__ e,
                                float* __restrict__ out, int n4) {
    int i = blockIdx.x * blockDim.x + threadIdx.x;
    if (i < n4) {
        reinterpret_cast<float4*>(out)[i] =
            reinterpret_cast<const float4*>(e)[i];
    }
}

__device__ __forceinline__ uint32_t smem_u32(const void* p) {
    return (uint32_t)__cvta_generic_to_shared(p);
}

__device__ __forceinline__ void mbar_init(uint32_t mbar, uint32_t count) {
    asm volatile("mbarrier.init.shared.b64 [%0], %1;" :: "r"(mbar), "r"(count) : "memory");
}
__device__ __forceinline__ void mbar_expect_tx(uint32_t mbar, uint32_t bytes) {
    asm volatile("mbarrier.arrive.expect_tx.shared.b64 _, [%0], %1;"
                 :: "r"(mbar), "r"(bytes) : "memory");
}
__device__ __forceinline__ void bulk_g2s(uint32_t dst_smem, const void* src,
                                         uint32_t bytes, uint32_t mbar) {
    asm volatile("cp.async.bulk.shared::cta.global.mbarrier::complete_tx::bytes "
                 "[%0], [%1], %2, [%3];"
                 :: "r"(dst_smem), "l"(src), "r"(bytes), "r"(mbar) : "memory");
}
__device__ __forceinline__ void mbar_wait(uint32_t mbar, uint32_t parity) {
    uint32_t done;
    asm volatile(
        "{\n\t.reg .pred p;\n\t"
        "mbarrier.try_wait.parity.acquire.cta.shared::cta.b64 p, [%1], %2;\n\t"
        "selp.b32 %0, 1, 0, p;\n\t}"
        : "=r"(done) : "r"(mbar), "r"(parity) : "memory");
    if (!done) {
        asm volatile(
            "{\n\t.reg .pred P1;\n\t"
            "W%=:\n\t"
            "mbarrier.try_wait.parity.acquire.cta.shared::cta.b64 P1, [%0], %1, 0x989680;\n\t"
            "@P1 bra.uni D%=;\n\t"
            "bra.uni W%=;\n\t"
            "D%=:\n\t}"
            :: "r"(mbar), "r"(parity) : "memory");
    }
}

__global__ void __launch_bounds__(TPB)
self_energy_segsum_kernel(const int* __restrict__ zs,
                          const int* __restrict__ seg,
                          const float* __restrict__ se,
                          float* __restrict__ out,
                          int n_atoms) {
    extern __shared__ __align__(128) char smem[];
    __shared__ __align__(8) unsigned long long mbar_store[TILES_PER_CTA];

    const int tid = threadIdx.x;
    const int n_tiles = n_atoms / TILE_ATOMS;
    const int first_tile = blockIdx.x * TILES_PER_CTA;
    int n_mine = n_tiles - first_tile;
    if (n_mine > TILES_PER_CTA) n_mine = TILES_PER_CTA;

    uint32_t mb[TILES_PER_CTA];
#pragma unroll
    for (int s = 0; s < TILES_PER_CTA; s++)
        mb[s] = smem_u32(&mbar_store[s]);

    if (tid == 0) {
#pragma unroll
        for (int s = 0; s < TILES_PER_CTA; s++) mbar_init(mb[s], 1);
    }
    __syncthreads();

    // Fire-and-forget ALL tile loads via bulk-async (TMA path, bypasses the
    // per-lane L1tex wavefront queue). 2 instructions per 16KB stage.
    if (tid == 0) {
        for (int s = 0; s < n_mine; s++) {
            long long abase = (long long)(first_tile + s) * TILE_ATOMS;
            mbar_expect_tx(mb[s], STAGE_BYTES);
            bulk_g2s(smem_u32(smem + s * STAGE_BYTES), zs + abase,
                     TILE_BYTES, mb[s]);
            bulk_g2s(smem_u32(smem + s * STAGE_BYTES + TILE_BYTES), seg + abase,
                     TILE_BYTES, mb[s]);
        }
    }

    // Consume stages in order; epilogue identical to the proven R3 run loop.
    for (int s = 0; s < n_mine; s++) {
        mbar_wait(mb[s], 0);

        const char* zt = smem + s * STAGE_BYTES;
        const char* st = smem + s * STAGE_BYTES + TILE_BYTES;
        int off = tid * 8;   // 8 atoms per thread per tile (2048/256)

        int4 zv0 = *reinterpret_cast<const int4*>(zt + off * 4);
        int4 zv1 = *reinterpret_cast<const int4*>(zt + off * 4 + 16);
        int4 sv0 = *reinterpret_cast<const int4*>(st + off * 4);
        int4 sv1 = *reinterpret_cast<const int4*>(st + off * 4 + 16);

        float e0 = __ldg(se + zv0.x), e1 = __ldg(se + zv0.y);
        float e2 = __ldg(se + zv0.z), e3 = __ldg(se + zv0.w);
        float e4 = __ldg(se + zv1.x), e5 = __ldg(se + zv1.y);
        float e6 = __ldg(se + zv1.z), e7 = __ldg(se + zv1.w);

        int   sarr[8] = {sv0.x, sv0.y, sv0.z, sv0.w, sv1.x, sv1.y, sv1.z, sv1.w};
        float earr[8] = {e0, e1, e2, e3, e4, e5, e6, e7};

        int cur_seg = sarr[0];
        float run_sum = 0.0f;
#pragma unroll
        for (int k = 0; k < 8; k++) {
            if (sarr[k] != cur_seg) {
                atomicAdd(out + cur_seg, run_sum);
                cur_seg = sarr[k];
                run_sum = 0.0f;
            }
            run_sum += earr[k];
        }
        atomicAdd(out + cur_seg, run_sum);
    }

    // Tail atoms beyond full tiles (none for 8388608, but be general).
    if (blockIdx.x == 0 && tid == 0) {
        long long tail_start = (long long)n_tiles * TILE_ATOMS;
        if (tail_start < n_atoms) {
            int cs = -1; float rs = 0.0f;
            for (long long i = tail_start; i < n_atoms; i++) {
                int sgv = seg[i];
                if (sgv != cs) { if (cs >= 0) atomicAdd(out + cs, rs); cs = sgv; rs = 0.0f; }
                rs += __ldg(se + zs[i]);
            }
            if (cs >= 0) atomicAdd(out + cs, rs);
        }
    }
}

extern "C" void kernel_launch(void* const* d_in, const int* in_sizes, int n_in,
                              void* d_out, int out_size) {
    const float* energy = (const float*)d_in[0];
    const int*   zs     = (const int*)d_in[1];
    const int*   seg    = (const int*)d_in[2];
    const float* se     = (const float*)d_in[3];
    float* out = (float*)d_out;

    int n_mol   = in_sizes[0];
    int n_atoms = in_sizes[1];

    // 1) out = energy_readout (d_out comes in poisoned). n_mol is 4-aligned.
    {
        int n4 = n_mol / 4;
        int blocks = (n4 + TPB - 1) / TPB;
        init_out_kernel<<<blocks, TPB>>>(energy, out, n4);
    }

    // 2) bulk-async staged segment sum (TMA path; L1tex queue bypassed)
    {
        static bool attr_set = false;
        if (!attr_set) {
            cudaFuncSetAttribute(self_energy_segsum_kernel,
                                 cudaFuncAttributeMaxDynamicSharedMemorySize,
                                 SMEM_DYN);
            attr_set = true;
        }
        int n_tiles = n_atoms / TILE_ATOMS;
        int blocks = (n_tiles + TILES_PER_CTA - 1) / TILES_PER_CTA;
        if (blocks < 1) blocks = 1;
        self_energy_segsum_kernel<<<blocks, TPB, SMEM_DYN>>>(zs, seg, se, out, n_atoms);
    }
}

// round 17
// speedup vs baseline: 1.0763x; 1.0763x over previous
#include <cuda_runtime.h>
#include <cuda_bf16.h>
#include <cstdint>

// Inputs (metadata order):
//   d_in[0] : energy_readout            float32 [262144]
//   d_in[1] : atomic_numbers            int32   [8388608]
//   d_in[2] : atomic_subsystem_indices  int32   [8388608]  (sorted ascending)
//   d_in[3] : self_energies_tensor      float32 [100]
// Output: float32 [262144] = energy_readout + segment_sum(se[Z], seg_idx)

#define CHUNK 8           // atoms per thread (exactly one chunk per thread)
#define TPB 128

__global__ void init_out_kernel(const float* __restrict__ e,
                                float* __restrict__ out, int n4) {
    int i = blockIdx.x * blockDim.x + threadIdx.x;
    if (i < n4) {
        reinterpret_cast<float4*>(out)[i] =
            reinterpret_cast<const float4*>(e)[i];
    }
}

__global__ void __launch_bounds__(TPB, 16)
self_energy_segsum_kernel(const int* __restrict__ zs,
                          const int* __restrict__ seg,
                          const float* __restrict__ se,
                          float* __restrict__ out,
                          int n_atoms) {
    long long base = (long long)(blockIdx.x * blockDim.x + threadIdx.x) * CHUNK;
    if (base >= n_atoms) return;

    if (base + CHUNK <= n_atoms) {
        // 256-bit loads: one LDG.E.256 per array per thread (32B each,
        // 32B-aligned because base is a multiple of 8 ints). Halves the
        // stream's LSU dispatch + L1tex wavefront count vs 2x LDG.128.
        ulonglong4 zv = *reinterpret_cast<const ulonglong4*>(zs + base);
        ulonglong4 sv = *reinterpret_cast<const ulonglong4*>(seg + base);

        int z0 = (int)(zv.x), z1 = (int)(zv.x >> 32);
        int z2 = (int)(zv.y), z3 = (int)(zv.y >> 32);
        int z4 = (int)(zv.z), z5 = (int)(zv.z >> 32);
        int z6 = (int)(zv.w), z7 = (int)(zv.w >> 32);
        int s0 = (int)(sv.x), s1 = (int)(sv.x >> 32);
        int s2 = (int)(sv.y), s3 = (int)(sv.y >> 32);
        int s4 = (int)(sv.z), s5 = (int)(sv.z >> 32);
        int s6 = (int)(sv.w), s7 = (int)(sv.w >> 32);

        // LUT gathers from the L1-resident 400B table.
        float e0 = __ldg(se + z0), e1 = __ldg(se + z1);
        float e2 = __ldg(se + z2), e3 = __ldg(se + z3);
        float e4 = __ldg(se + z4), e5 = __ldg(se + z5);
        float e6 = __ldg(se + z6), e7 = __ldg(se + z7);

        int   s[8] = {s0, s1, s2, s3, s4, s5, s6, s7};
        float e[8] = {e0, e1, e2, e3, e4, e5, e6, e7};

        int cur_seg = s[0];
        float run_sum = 0.0f;
#pragma unroll
        for (int k = 0; k < 8; k++) {
            if (s[k] != cur_seg) {
                atomicAdd(out + cur_seg, run_sum);   // interior run boundary
                cur_seg = s[k];
                run_sum = 0.0f;
            }
            run_sum += e[k];
        }
        atomicAdd(out + cur_seg, run_sum);           // trailing run
    } else {
        // Tail safety (not hit for 8388608 atoms, but be general)
        int cs = -1; float rs = 0.0f;
        for (long long i = base; i < n_atoms; i++) {
            int s = seg[i];
            if (s != cs) { if (cs >= 0) atomicAdd(out + cs, rs); cs = s; rs = 0.0f; }
            rs += __ldg(se + zs[i]);
        }
        if (cs >= 0) atomicAdd(out + cs, rs);
    }
}

extern "C" void kernel_launch(void* const* d_in, const int* in_sizes, int n_in,
                              void* d_out, int out_size) {
    const float* energy = (const float*)d_in[0];
    const int*   zs     = (const int*)d_in[1];
    const int*   seg    = (const int*)d_in[2];
    const float* se     = (const float*)d_in[3];
    float* out = (float*)d_out;

    int n_mol   = in_sizes[0];
    int n_atoms = in_sizes[1];

    // 1) out = energy_readout (d_out comes in poisoned). n_mol is 4-aligned.
    {
        int n4 = n_mol / 4;
        int blocks = (n4 + TPB - 1) / TPB;
        init_out_kernel<<<blocks, TPB>>>(energy, out, n4);
    }

    // 2) one-chunk-per-thread segment sum with 256-bit stream loads
    {
        long long threads_needed = ((long long)n_atoms + CHUNK - 1) / CHUNK;
        int blocks = (int)((threads_needed + TPB - 1) / TPB);
        self_energy_segsum_kernel<<<blocks, TPB>>>(zs, seg, se, out, n_atoms);
    }
}